// round 3
// baseline (speedup 1.0000x reference)
#include <cuda_runtime.h>
#include <math.h>

// ---------------- constants ----------------
#define VOX   2097152          // 128^3
#define CCH   48               // feature channels
#define NPOS  4736             // 4096 + 512 + 128(pad) positions per batch
#define OFF0  0
#define OFF1  4096
#define OFF2  4608

// ---------------- device scratch (no allocations allowed) ----------------
__device__ double g_inter[6];           // [b][c] dice intersection
__device__ double g_psum[6];            // [b][c] softmax sums
__device__ double g_vcnt[6];            // [b][c] one-hot counts
__device__ double g_S[54];              // [b][scale][a*3+bcls] upper-tri class-pair sums
__device__ int    g_ccnt[18];           // [b][scale][cls]
__device__ float  g_fnorm[2 * NPOS * CCH];
__device__ int    g_cls[2 * NPOS];

// ---------------- zero accumulators ----------------
__global__ void zero_kernel() {
    int t = threadIdx.x;
    if (t < 6)  { g_inter[t] = 0.0; g_psum[t] = 0.0; g_vcnt[t] = 0.0; }
    if (t < 54) g_S[t] = 0.0;
    if (t < 18) g_ccnt[t] = 0;
}

// ---------------- dice: streaming softmax reduction ----------------
// target is int32 (JAX x64 disabled downcasts the declared int64).
__global__ void dice_kernel(const float* __restrict__ pred,
                            const int* __restrict__ tgt) {
    const int b = blockIdx.y;
    const int Q = VOX / 4;
    float fi0 = 0.f, fi1 = 0.f, fi2 = 0.f;
    float fp0 = 0.f, fp1 = 0.f, fp2 = 0.f;
    float fc0 = 0.f, fc1 = 0.f, fc2 = 0.f;
    const float4* P  = (const float4*)pred;
    const int4*   T4 = (const int4*)tgt;

    for (int q = blockIdx.x * blockDim.x + threadIdx.x; q < Q;
         q += gridDim.x * blockDim.x) {
        float4 x0 = P[(size_t)(b * 3 + 0) * Q + q];
        float4 x1 = P[(size_t)(b * 3 + 1) * Q + q];
        float4 x2 = P[(size_t)(b * 3 + 2) * Q + q];
        int4   tv = T4[(size_t)b * Q + q];

#define DO_VOXEL(pa, pb, pc, tt)                                           \
        {                                                                  \
            float m  = fmaxf(pa, fmaxf(pb, pc));                           \
            float e0 = __expf(pa - m);                                     \
            float e1 = __expf(pb - m);                                     \
            float e2 = __expf(pc - m);                                     \
            float inv = 1.f / (e0 + e1 + e2);                              \
            e0 *= inv; e1 *= inv; e2 *= inv;                               \
            fp0 += e0; fp1 += e1; fp2 += e2;                               \
            int tc = (tt) < 0 ? 0 : (tt);                                  \
            if (tc == 0)      { fi0 += e0; fc0 += 1.f; }                   \
            else if (tc == 1) { fi1 += e1; fc1 += 1.f; }                   \
            else              { fi2 += e2; fc2 += 1.f; }                   \
        }
        DO_VOXEL(x0.x, x1.x, x2.x, tv.x);
        DO_VOXEL(x0.y, x1.y, x2.y, tv.y);
        DO_VOXEL(x0.z, x1.z, x2.z, tv.z);
        DO_VOXEL(x0.w, x1.w, x2.w, tv.w);
#undef DO_VOXEL
    }

    float v[9] = { fi0, fi1, fi2, fp0, fp1, fp2, fc0, fc1, fc2 };
#pragma unroll
    for (int o = 16; o; o >>= 1)
#pragma unroll
        for (int q = 0; q < 9; q++)
            v[q] += __shfl_down_sync(0xffffffffu, v[q], o);

    __shared__ float red[8][9];
    int w = threadIdx.x >> 5, l = threadIdx.x & 31;
    if (l == 0)
#pragma unroll
        for (int q = 0; q < 9; q++) red[w][q] = v[q];
    __syncthreads();
    if (threadIdx.x < 9) {
        float s = 0.f;
#pragma unroll
        for (int w2 = 0; w2 < 8; w2++) s += red[w2][threadIdx.x];
        int q = threadIdx.x;
        if (q < 3)      atomicAdd(&g_inter[b * 3 + q],     (double)s);
        else if (q < 6) atomicAdd(&g_psum[b * 3 + q - 3],  (double)s);
        else            atomicAdd(&g_vcnt[b * 3 + q - 6],  (double)s);
    }
}

// ---------------- prep: normalize features + mask classes + counts ----------------
__global__ void prep_kernel(const float* __restrict__ fmap,
                            const int* __restrict__ tgt,
                            int scaleIdx, int D, int s, int N, int off, int Npad) {
    int gid = blockIdx.x * blockDim.x + threadIdx.x;
    if (gid >= 2 * Npad) return;
    int b = gid / Npad, n = gid % Npad;
    int base = (b * NPOS + off + n) * CCH;
    if (n >= N) {
#pragma unroll
        for (int c = 0; c < CCH; c++) g_fnorm[base + c] = 0.f;
        g_cls[b * NPOS + off + n] = 3;
        return;
    }
    int z = n / (D * D), y = (n / D) % D, x = n % D;
    int tv = tgt[(size_t)b * VOX + ((size_t)(z * s) * 128 + y * s) * 128 + x * s];
    int cls = tv < 0 ? 0 : (tv > 2 ? 2 : tv);
    g_cls[b * NPOS + off + n] = cls;
    atomicAdd(&g_ccnt[(b * 3 + scaleIdx) * 3 + cls], 1);

    float v[CCH];
    float ss = 0.f;
#pragma unroll
    for (int c = 0; c < CCH; c++) {
        v[c] = fmap[((size_t)b * CCH + c) * N + n];
        ss = fmaf(v[c], v[c], ss);
    }
    float inv = 1.f / fmaxf(sqrtf(ss), 1e-12f);
#pragma unroll
    for (int c = 0; c < CCH; c++) g_fnorm[base + c] = v[c] * inv;
}

// ---------------- packed f32x2 FMA ----------------
__device__ __forceinline__ void ffma2(unsigned long long& d,
                                      unsigned long long a,
                                      unsigned long long b) {
    asm("fma.rn.f32x2 %0, %1, %2, %0;" : "+l"(d) : "l"(a), "l"(b));
}

// ---------------- gram: fused dot -> exp -> class-pair sums ----------------
// tile 128x128 (upper triangle of block grid), 8x8 microtile, f32x2 FMA.
#define BS_STRIDE 50
__global__ void __launch_bounds__(256, 1)
gram_kernel(int off, int scaleIdx) {
    int by = blockIdx.y, bx = blockIdx.x, b = blockIdx.z;
    if (by > bx) return;

    extern __shared__ float sm[];
    float* As = sm;                         // [128][48] contiguous
    float* Bs = sm + 128 * 48;              // [128][BS_STRIDE]
    float* wr = Bs + 128 * BS_STRIDE;       // [3][128] row one-hot
    float* wc = wr + 3 * 128;               // [3][128] col one-hot

    int tid = threadIdx.x;
    const float4* FR4 = (const float4*)(g_fnorm + ((size_t)b * NPOS + off + by * 128) * CCH);
    const float4* FC4 = (const float4*)(g_fnorm + ((size_t)b * NPOS + off + bx * 128) * CCH);

    for (int t = tid; t < 128 * 12; t += 256)
        ((float4*)As)[t] = FR4[t];
    for (int t = tid; t < 128 * 12; t += 256) {
        int r = t / 12, kq = t % 12;
        float4 vv = FC4[t];
        float* dst = Bs + r * BS_STRIDE + kq * 4;
        dst[0] = vv.x; dst[1] = vv.y; dst[2] = vv.z; dst[3] = vv.w;
    }
    if (tid < 128) {
        int cr = g_cls[b * NPOS + off + by * 128 + tid];
        wr[tid]       = (cr == 0) ? 1.f : 0.f;
        wr[128 + tid] = (cr == 1) ? 1.f : 0.f;
        wr[256 + tid] = (cr == 2) ? 1.f : 0.f;
    } else {
        int t2 = tid - 128;
        int cc = g_cls[b * NPOS + off + bx * 128 + t2];
        wc[t2]       = (cc == 0) ? 1.f : 0.f;
        wc[128 + t2] = (cc == 1) ? 1.f : 0.f;
        wc[256 + t2] = (cc == 2) ? 1.f : 0.f;
    }
    __syncthreads();

    int ty = tid >> 4, tx = tid & 15;   // rows: ty + i*16, cols: tx + j*16

    unsigned long long acc[8][8];
#pragma unroll
    for (int i = 0; i < 8; i++)
#pragma unroll
        for (int j = 0; j < 8; j++) acc[i][j] = 0ull;

#pragma unroll 4
    for (int k = 0; k < CCH; k += 2) {
        unsigned long long a2[8], b2[8];
#pragma unroll
        for (int i = 0; i < 8; i++)
            a2[i] = *(const unsigned long long*)(As + (ty + i * 16) * 48 + k);
#pragma unroll
        for (int j = 0; j < 8; j++)
            b2[j] = *(const unsigned long long*)(Bs + (tx + j * 16) * BS_STRIDE + k);
#pragma unroll
        for (int i = 0; i < 8; i++)
#pragma unroll
            for (int j = 0; j < 8; j++) ffma2(acc[i][j], a2[i], b2[j]);
    }

    float lacc[9];
#pragma unroll
    for (int q = 0; q < 9; q++) lacc[q] = 0.f;

    bool diag = (by == bx);
#pragma unroll
    for (int i = 0; i < 8; i++) {
        int rl = ty + i * 16;
        float w0r = wr[rl], w1r = wr[128 + rl], w2r = wr[256 + rl];
        float rs0 = 0.f, rs1 = 0.f, rs2 = 0.f;
#pragma unroll
        for (int j = 0; j < 8; j++) {
            int ml = tx + j * 16;
            unsigned long long u = acc[i][j];
            float lo = __uint_as_float((unsigned)(u & 0xffffffffu));
            float hi = __uint_as_float((unsigned)(u >> 32));
            float dot = lo + hi;
            float E = exp2f(dot * 14.4269504088896340736f);   // exp(dot/0.1)
            if (diag && ml <= rl) E = 0.f;                    // strict upper triangle
            rs0 = fmaf(E, wc[ml],       rs0);
            rs1 = fmaf(E, wc[128 + ml], rs1);
            rs2 = fmaf(E, wc[256 + ml], rs2);
        }
        lacc[0] = fmaf(w0r, rs0, lacc[0]);
        lacc[1] = fmaf(w0r, rs1, lacc[1]);
        lacc[2] = fmaf(w0r, rs2, lacc[2]);
        lacc[3] = fmaf(w1r, rs0, lacc[3]);
        lacc[4] = fmaf(w1r, rs1, lacc[4]);
        lacc[5] = fmaf(w1r, rs2, lacc[5]);
        lacc[6] = fmaf(w2r, rs0, lacc[6]);
        lacc[7] = fmaf(w2r, rs1, lacc[7]);
        lacc[8] = fmaf(w2r, rs2, lacc[8]);
    }

#pragma unroll
    for (int o = 16; o; o >>= 1)
#pragma unroll
        for (int q = 0; q < 9; q++)
            lacc[q] += __shfl_down_sync(0xffffffffu, lacc[q], o);

    __shared__ float rsum[8][9];
    int w = tid >> 5, l = tid & 31;
    if (l == 0)
#pragma unroll
        for (int q = 0; q < 9; q++) rsum[w][q] = lacc[q];
    __syncthreads();
    if (tid < 9) {
        float s = 0.f;
#pragma unroll
        for (int w2 = 0; w2 < 8; w2++) s += rsum[w2][tid];
        atomicAdd(&g_S[(b * 3 + scaleIdx) * 9 + tid], (double)s);
    }
}

// ---------------- finalize ----------------
__device__ double pair_loss(double S, double cnt, bool positive) {
    if (!(cnt > 0.0)) return 0.0;
    double mean = S / (cnt < 1.0 ? 1.0 : cnt);
    return positive ? -log(mean + 1e-6) : log1p(mean);
}

__global__ void finalize_kernel(const float* __restrict__ logits,
                                const int* __restrict__ labels,
                                float* __restrict__ out) {
    // dice
    double dsum = 0.0;
    for (int b = 0; b < 2; b++)
        for (int c = 1; c < 3; c++) {
            double d = (2.0 * g_inter[b * 3 + c] + 1e-5) /
                       (g_psum[b * 3 + c] + g_vcnt[b * 3 + c] + 1e-5);
            dsum += d;
        }
    double dice = 1.0 - dsum / 4.0;

    // focal
    double fsum = 0.0;
    for (int i = 0; i < 6; i++) {
        double x  = (double)logits[i];
        double pt = 1.0 / (1.0 + exp(-x));
        if (labels[i] != 1) pt = 1.0 - pt;
        double om = 1.0 - pt;
        fsum += -0.25 * om * om * log(pt + 1e-6);
    }
    double focal = fsum / 6.0;

    // contrastive
    const double wsc[3] = { 1.0, 0.8, 0.6 };
    double contr = 0.0;
    for (int sc = 0; sc < 3; sc++) {
        double sl = 0.0;
        for (int b = 0; b < 2; b++) {
            const double* T = g_S + (b * 3 + sc) * 9;
            const int* cc = g_ccnt + (b * 3 + sc) * 3;
            double c0 = cc[0], c1 = cc[1], c2 = cc[2];
            sl += pair_loss(2.0 * T[4],     c1 * c1 - c1, true);
            sl += pair_loss(2.0 * T[8],     c2 * c2 - c2, true);
            sl += pair_loss(T[5] + T[7],    c1 * c2,      false);
            sl += pair_loss(T[1] + T[3],    c0 * c1,      false);
            sl += pair_loss(T[2] + T[6],    c0 * c2,      false);
        }
        contr += wsc[sc] * (sl * 0.5);
    }

    double total = 1.0 * dice + 1.0 * focal + 0.1 * contr;
    out[0] = (float)total;
    out[1] = (float)dice;
    out[2] = (float)focal;
    out[3] = (float)contr;
}

// ---------------- launcher ----------------
extern "C" void kernel_launch(void* const* d_in, const int* in_sizes, int n_in,
                              void* d_out, int out_size) {
    const float* pred   = (const float*)d_in[0];
    const int*   tgt    = (const int*)d_in[1];
    const float* f0     = (const float*)d_in[2];
    const float* f1     = (const float*)d_in[3];
    const float* f2     = (const float*)d_in[4];
    const float* logits = (const float*)d_in[5];
    const int*   labels = (const int*)d_in[6];
    float*       out    = (float*)d_out;

    const int smemBytes = (128 * 48 + 128 * BS_STRIDE + 6 * 128) * sizeof(float);
    cudaFuncSetAttribute(gram_kernel,
                         cudaFuncAttributeMaxDynamicSharedMemorySize, smemBytes);

    zero_kernel<<<1, 128>>>();
    dice_kernel<<<dim3(1024, 2), 256>>>(pred, tgt);

    // scale 0: D=16, s=8, N=4096 ; scale 1: D=8, s=16, N=512 ; scale 2: D=4, s=32, N=64 (pad 128)
    prep_kernel<<<32, 256>>>(f0, tgt, 0, 16, 8,  4096, OFF0, 4096);
    prep_kernel<<<4,  256>>>(f1, tgt, 1, 8,  16, 512,  OFF1, 512);
    prep_kernel<<<1,  256>>>(f2, tgt, 2, 4,  32, 64,   OFF2, 128);

    gram_kernel<<<dim3(32, 32, 2), 256, smemBytes>>>(OFF0, 0);
    gram_kernel<<<dim3(4, 4, 2),   256, smemBytes>>>(OFF1, 1);
    gram_kernel<<<dim3(1, 1, 2),   256, smemBytes>>>(OFF2, 2);

    finalize_kernel<<<1, 1>>>(logits, labels, out);
}